// round 4
// baseline (speedup 1.0000x reference)
#include <cuda_runtime.h>
#include <math.h>

// ---------------------------------------------------------------------------
// Problem constants (fixed shapes from setup_inputs)
// ---------------------------------------------------------------------------
#define TT      4096   // sequence length T
#define NHEADS  16
#define BB      4      // batch
#define BH      64     // B * NHEADS
#define DPH     64     // head dim
#define HID     1024   // hidden H
#define NHASH   2
#define NBUCK   64     // n_buckets
#define WW      64     // bucket_size W
#define CCHUNK  128    // NHASH * NBUCK chunks per bh
#define MTOT    16384  // B * T rows of the big GEMMs

// ---------------------------------------------------------------------------
// Device scratch (static; no cudaMalloc allowed).
// g_qk is reused as the combine output buffer [b,t,n,d] after attention --
// qk data is dead by then (attention consumed it into g_o / g_lse).
// ---------------------------------------------------------------------------
__device__ float          g_qk  [(size_t)BH * TT * DPH];          //  67 MB (later: comb)
__device__ float          g_v   [(size_t)BH * TT * DPH];          //  67 MB
__device__ float          g_o   [(size_t)BH * NHASH * TT * DPH];  // 134 MB
__device__ float          g_lse [(size_t)BH * NHASH * TT];        //   2 MB
__device__ int            g_st  [(size_t)BH * NHASH * TT];        //   2 MB
__device__ unsigned char  g_bkt [(size_t)BH * NHASH * TT];        // 512 KB

// ---------------------------------------------------------------------------
// 128x128x8 fp32 SGEMM, 256 threads, 8x8 per thread, register-prefetched
// global loads (next K-tile loads issued before current tile's compute).
// mode 0: C row-major [M,N]
// mode 1: C remapped to per-head layout [bh, t, d]:
//         m = b*T+t, col = n*64+d -> C[((b*16+n)*T + t)*64 + d]
// ---------------------------------------------------------------------------
__global__ __launch_bounds__(256)
void sgemm_k(const float* __restrict__ A, const float* __restrict__ B,
             float* __restrict__ C, int M, int N, int K, int mode)
{
    __shared__ __align__(16) float As[8][128];
    __shared__ __align__(16) float Bs[8][128];

    const int tid  = threadIdx.x;
    const int brow = blockIdx.y * 128;
    const int bcol = blockIdx.x * 128;
    const int tr   = (tid >> 4) * 8;
    const int tc   = (tid & 15) * 8;

    const int a_row = tid >> 1;
    const int a_col = (tid & 1) * 4;
    const int b_row = tid >> 5;
    const int b_col = (tid & 31) * 4;

    const float* Ap = A + (size_t)(brow + a_row) * K + a_col;
    const float* Bp = B + (size_t)b_row * N + bcol + b_col;

    float acc[8][8];
#pragma unroll
    for (int y = 0; y < 8; y++)
#pragma unroll
        for (int x = 0; x < 8; x++) acc[y][x] = 0.f;

    // prologue: first tile's loads
    float4 av = *(const float4*)Ap;  Ap += 8;
    float4 bv = *(const float4*)Bp;  Bp += (size_t)8 * N;

    for (int k0 = 0; k0 < K; k0 += 8) {
        As[a_col + 0][a_row] = av.x;
        As[a_col + 1][a_row] = av.y;
        As[a_col + 2][a_row] = av.z;
        As[a_col + 3][a_row] = av.w;
        *(float4*)&Bs[b_row][b_col] = bv;
        __syncthreads();

        // prefetch next K-tile while computing this one
        if (k0 + 8 < K) {
            av = *(const float4*)Ap;  Ap += 8;
            bv = *(const float4*)Bp;  Bp += (size_t)8 * N;
        }

#pragma unroll
        for (int kk = 0; kk < 8; kk++) {
            float4 a0 = *(const float4*)&As[kk][tr];
            float4 a1 = *(const float4*)&As[kk][tr + 4];
            float4 b0 = *(const float4*)&Bs[kk][tc];
            float4 b1 = *(const float4*)&Bs[kk][tc + 4];
            float ar[8] = {a0.x, a0.y, a0.z, a0.w, a1.x, a1.y, a1.z, a1.w};
            float br[8] = {b0.x, b0.y, b0.z, b0.w, b1.x, b1.y, b1.z, b1.w};
#pragma unroll
            for (int y = 0; y < 8; y++)
#pragma unroll
                for (int x = 0; x < 8; x++) acc[y][x] += ar[y] * br[x];
        }
        __syncthreads();
    }

    if (mode == 0) {
#pragma unroll
        for (int y = 0; y < 8; y++) {
            float* cp = C + (size_t)(brow + tr + y) * N + bcol + tc;
            *(float4*)(cp)     = make_float4(acc[y][0], acc[y][1], acc[y][2], acc[y][3]);
            *(float4*)(cp + 4) = make_float4(acc[y][4], acc[y][5], acc[y][6], acc[y][7]);
        }
    } else {
        // col tile of 8 stays inside a single head (tc multiple of 8, head = 64)
#pragma unroll
        for (int y = 0; y < 8; y++) {
            int m = brow + tr + y;
            int b = m >> 12;           // / T
            int t = m & (TT - 1);
            int col0 = bcol + tc;
            int n = col0 >> 6;
            int d = col0 & 63;
            float* cp = C + (((size_t)(b * NHEADS + n) * TT + t) * DPH + d);
            *(float4*)(cp)     = make_float4(acc[y][0], acc[y][1], acc[y][2], acc[y][3]);
            *(float4*)(cp + 4) = make_float4(acc[y][4], acc[y][5], acc[y][6], acc[y][7]);
        }
    }
}

// ---------------------------------------------------------------------------
// LSH bucketize: per token compute 64 rotations, argmax over [r, -r] per hash.
// One thread per token; rot cached in smem.
// ---------------------------------------------------------------------------
__global__ __launch_bounds__(128)
void bucketize_k(const float* __restrict__ rot)
{
    __shared__ float rs[DPH * 64];   // rot[d][h*32+r], 16 KB
    const int tid = threadIdx.x;
    for (int x = tid; x < DPH * 64; x += 128) rs[x] = rot[x];
    __syncthreads();

    const int gid = blockIdx.x * 128 + tid;     // 0 .. BH*T-1
    const int bh  = gid >> 12;
    const int t   = gid & (TT - 1);

    const float* qrow = g_qk + ((size_t)bh * TT + t) * DPH;

    float vals[64];
#pragma unroll
    for (int x = 0; x < 64; x++) vals[x] = 0.f;

    for (int d = 0; d < DPH; d++) {
        float qd = qrow[d];
        const float* rr = rs + d * 64;
#pragma unroll
        for (int x = 0; x < 64; x++) vals[x] += qd * rr[x];
    }

#pragma unroll
    for (int h = 0; h < NHASH; h++) {
        float best = -INFINITY;
        int   bi   = 0;
#pragma unroll
        for (int idx = 0; idx < 64; idx++) {
            float vv = (idx < 32) ? vals[h * 32 + idx] : -vals[h * 32 + idx - 32];
            if (vv > best) { best = vv; bi = idx; }   // first max wins (jnp.argmax)
        }
        g_bkt[((size_t)(bh * NHASH + h)) * TT + t] = (unsigned char)bi;
    }
}

// ---------------------------------------------------------------------------
// Stable counting sort of 4096 tokens by bucket (64 bins), per (bh, hash).
// One block (128 threads) per segment; each thread owns 32 consecutive tokens.
// ---------------------------------------------------------------------------
__global__ __launch_bounds__(128)
void sort_k()
{
    const int seg = blockIdx.x;        // bh*2 + h
    const int tid = threadIdx.x;
    __shared__ int hist[NBUCK * 128];  // [bucket][thread]
    __shared__ int btot[NBUCK];

    const unsigned char* bk = g_bkt + (size_t)seg * TT;

    for (int x = tid; x < NBUCK * 128; x += 128) hist[x] = 0;
    __syncthreads();

    const int t0 = tid * 32;
    for (int j = 0; j < 32; j++) {
        int b = bk[t0 + j];
        hist[b * 128 + tid]++;
    }
    __syncthreads();

    if (tid < NBUCK) {
        int s = 0;
        for (int j = 0; j < 128; j++) s += hist[tid * 128 + j];
        btot[tid] = s;
    }
    __syncthreads();

    if (tid == 0) {
        int run = 0;
        for (int b = 0; b < NBUCK; b++) { int c = btot[b]; btot[b] = run; run += c; }
    }
    __syncthreads();

    if (tid < NBUCK) {
        int run = btot[tid];
        for (int j = 0; j < 128; j++) {
            int c = hist[tid * 128 + j];
            hist[tid * 128 + j] = run;
            run += c;
        }
    }
    __syncthreads();

    int* dst = g_st + (size_t)(seg >> 1) * (NHASH * TT) + (size_t)(seg & 1) * TT;
    for (int j = 0; j < 32; j++) {
        int t = t0 + j;
        int b = bk[t];
        int pos = hist[b * 128 + tid]++;
        dst[pos] = t;
    }
}

// ---------------------------------------------------------------------------
// Chunked LSH attention with one-chunk look-back.
// grid = (128 chunks, 64 bh), block = 64 threads (one per query row).
// Keys = L2-normalized qk of [chunk c, chunk (c-1) mod 128].
// Online softmax; outputs normalized bo + lse, scattered to original (h, t).
// ---------------------------------------------------------------------------
__global__ __launch_bounds__(64)
void attn_k(const unsigned char* __restrict__ pad)
{
    const int c  = blockIdx.x;
    const int bh = blockIdx.y;
    const int i  = threadIdx.x;
    const int b  = bh >> 4;

    __shared__ __align__(16) float ks[WW][68];  // padded stride: no store conflicts
    __shared__ __align__(16) float vs[WW][68];
    __shared__ int   tks[WW];
    __shared__ float pen[WW];

    const int* stb = g_st + (size_t)bh * (NHASH * TT);

    const int sq = c * WW + i;
    const int tq = stb[sq];

    float4 q4[16];
    {
        const float4* qrow = (const float4*)(g_qk + ((size_t)bh * TT + tq) * DPH);
#pragma unroll
        for (int x = 0; x < 16; x++) q4[x] = qrow[x];
    }

    float m = -INFINITY, l = 0.f;
    float acc[DPH];
#pragma unroll
    for (int d = 0; d < DPH; d++) acc[d] = 0.f;

    for (int stg = 0; stg < 2; stg++) {
        const int kc = (stg == 0) ? c : ((c + CCHUNK - 1) & (CCHUNK - 1));
        const int sk = kc * WW + i;
        const int tk = stb[sk];

        {
            const float4* krow = (const float4*)(g_qk + ((size_t)bh * TT + tk) * DPH);
            const float4* vrow = (const float4*)(g_v  + ((size_t)bh * TT + tk) * DPH);
            float4 kr[16];
            float ss = 0.f;
#pragma unroll
            for (int x = 0; x < 16; x++) {
                kr[x] = krow[x];
                ss += kr[x].x * kr[x].x + kr[x].y * kr[x].y
                    + kr[x].z * kr[x].z + kr[x].w * kr[x].w;
            }
            float inv = 1.f / fmaxf(sqrtf(ss), 1e-6f);
#pragma unroll
            for (int x = 0; x < 16; x++) {
                *(float4*)&ks[i][4 * x] = make_float4(kr[x].x * inv, kr[x].y * inv,
                                                      kr[x].z * inv, kr[x].w * inv);
                *(float4*)&vs[i][4 * x] = vrow[x];
            }
            tks[i] = tk;
            pen[i] = pad[(size_t)b * TT + tk] ? -1e9f : 0.f;
        }
        __syncthreads();

        for (int j = 0; j < WW; j++) {
            const float* kj = ks[j];
            float s = 0.f;
#pragma unroll
            for (int x = 0; x < 16; x++) {
                s += q4[x].x * kj[4 * x + 0] + q4[x].y * kj[4 * x + 1]
                   + q4[x].z * kj[4 * x + 2] + q4[x].w * kj[4 * x + 3];
            }
            s = s * 0.125f + pen[j];
            if (tq == tks[j]) s -= 1e5f;

            const float* vj = vs[j];
            if (s <= m) {
                float p = __expf(s - m);
                l += p;
#pragma unroll
                for (int d = 0; d < DPH; d++) acc[d] += p * vj[d];
            } else {
                float sc = __expf(m - s);   // exp(-inf)=0 handles first iter
                l = l * sc + 1.f;
#pragma unroll
                for (int d = 0; d < DPH; d++) acc[d] = acc[d] * sc + vj[d];
                m = s;
            }
        }
        __syncthreads();
    }

    const float lse  = m + __logf(l);
    const float invl = 1.f / l;
    const int   h    = sq >> 12;     // sorted index / T

    float* orow = g_o + (((size_t)(bh * NHASH + h)) * TT + tq) * DPH;
#pragma unroll
    for (int d = 0; d < DPH; d++) orow[d] = acc[d] * invl;
    g_lse[((size_t)(bh * NHASH + h)) * TT + tq] = lse;
}

// ---------------------------------------------------------------------------
// Combine the NHASH=2 rounds with softmax(lse) weights; write [b,t,n,d]
// into g_qk (reused -- qk data is dead after attn_k).
// ---------------------------------------------------------------------------
__global__ __launch_bounds__(256)
void combine_k()
{
    const size_t idx = (size_t)blockIdx.x * 256 + threadIdx.x; // BH*T*DPH
    const int d   = (int)(idx & 63);
    const size_t row = idx >> 6;           // bh*T + t
    const int bh  = (int)(row >> 12);
    const int t   = (int)(row & (TT - 1));

    const float l0 = g_lse[((size_t)(bh * 2 + 0)) * TT + t];
    const float l1 = g_lse[((size_t)(bh * 2 + 1)) * TT + t];
    const float mm = fmaxf(l0, l1);
    const float e0 = __expf(l0 - mm), e1 = __expf(l1 - mm);
    const float inv = 1.f / (e0 + e1);

    const float v0 = g_o[(((size_t)(bh * 2 + 0)) * TT + t) * DPH + d];
    const float v1 = g_o[(((size_t)(bh * 2 + 1)) * TT + t) * DPH + d];

    const int b = bh >> 4, n = bh & 15;
    g_qk[(((size_t)(b * TT + t)) * NHEADS + n) * DPH + d] = (e0 * v0 + e1 * v1) * inv;
}

// ---------------------------------------------------------------------------
// Host entry
// ---------------------------------------------------------------------------
extern "C" void kernel_launch(void* const* d_in, const int* in_sizes, int n_in,
                              void* d_out, int out_size)
{
    const float*         x    = (const float*)d_in[0];         // [B,T,H]
    const unsigned char* pad  = (const unsigned char*)d_in[1]; // [B,T] bool
    const float*         wqk  = (const float*)d_in[2];         // [H,NH,DPH] -> [1024,1024]
    const float*         wv   = (const float*)d_in[3];
    const float*         wo   = (const float*)d_in[4];         // [NH,DPH,H] -> [1024,1024]
    const float*         rot  = (const float*)d_in[5];         // [DPH,2,32]
    float*               out  = (float*)d_out;                 // [B,T,H]

    void *p_qk, *p_v;
    cudaGetSymbolAddress(&p_qk, g_qk);
    cudaGetSymbolAddress(&p_v,  g_v);

    // 1) qk / v projections: [16384,1024] x [1024,1024], remapped epilogue
    dim3 gg(HID / 128, MTOT / 128);
    sgemm_k<<<gg, 256>>>(x, wqk, (float*)p_qk, MTOT, HID, HID, 1);
    sgemm_k<<<gg, 256>>>(x, wv,  (float*)p_v,  MTOT, HID, HID, 1);

    // 2) LSH bucketing
    bucketize_k<<<(BH * TT) / 128, 128>>>(rot);

    // 3) stable counting sort per (bh, hash)
    sort_k<<<BH * NHASH, 128>>>();

    // 4) chunked attention with look-back
    dim3 ga(CCHUNK, BH);
    attn_k<<<ga, 64>>>(pad);

    // 5) combine hash rounds -> [b,t,n,d] into g_qk (reuse)
    combine_k<<<((size_t)BH * TT * DPH) / 256, 256>>>();

    // 6) output projection
    sgemm_k<<<gg, 256>>>((const float*)p_qk, wo, out, MTOT, HID, HID, 0);
}

// round 5
// speedup vs baseline: 1.0121x; 1.0121x over previous
#include <cuda_runtime.h>
#include <math.h>

// ---------------------------------------------------------------------------
// Problem constants (fixed shapes from setup_inputs)
// ---------------------------------------------------------------------------
#define TT      4096   // sequence length T
#define NHEADS  16
#define BB      4      // batch
#define BH      64     // B * NHEADS
#define DPH     64     // head dim
#define HID     1024   // hidden H
#define NHASH   2
#define NBUCK   64     // n_buckets
#define WW      64     // bucket_size W
#define CCHUNK  128    // NHASH * NBUCK chunks per bh
#define MTOT    16384  // B * T rows of the big GEMMs

typedef unsigned long long u64;

// ---- packed fp32x2 helpers (FFMA2 path: 2x fp32 FMA throughput) -----------
__device__ __forceinline__ void fma2(u64& d, u64 a, u64 b) {
    asm("fma.rn.f32x2 %0, %1, %2, %0;" : "+l"(d) : "l"(a), "l"(b));
}
__device__ __forceinline__ u64 fma2o(u64 a, u64 b, u64 c) {
    u64 d; asm("fma.rn.f32x2 %0, %1, %2, %3;" : "=l"(d) : "l"(a), "l"(b), "l"(c));
    return d;
}
__device__ __forceinline__ u64 bcast2(float f) {
    u64 r; unsigned int u = __float_as_uint(f);
    asm("mov.b64 %0, {%1, %1};" : "=l"(r) : "r"(u));
    return r;
}
__device__ __forceinline__ float2 unpack2(u64 v) {
    unsigned int lo, hi;
    asm("mov.b64 {%0, %1}, %2;" : "=r"(lo), "=r"(hi) : "l"(v));
    return make_float2(__uint_as_float(lo), __uint_as_float(hi));
}

// ---------------------------------------------------------------------------
// Device scratch (static; no cudaMalloc allowed).
// g_qk is reused as the combine output buffer [b,t,n,d] after attention.
// ---------------------------------------------------------------------------
__device__ float          g_qk  [(size_t)BH * TT * DPH];          //  67 MB (later: comb)
__device__ float          g_v   [(size_t)BH * TT * DPH];          //  67 MB
__device__ float          g_o   [(size_t)BH * NHASH * TT * DPH];  // 134 MB
__device__ float          g_lse [(size_t)BH * NHASH * TT];        //   2 MB
__device__ int            g_st  [(size_t)BH * NHASH * TT];        //   2 MB
__device__ unsigned char  g_bkt [(size_t)BH * NHASH * TT];        // 512 KB

// ---------------------------------------------------------------------------
// 128x128x8 fp32 SGEMM, 256 threads, 8x8 per thread, FFMA2 inner loop.
// Accumulators are y-paired f32x2: acc2[y2][x] holds rows (2*y2, 2*y2+1).
// mode 0: C row-major [M,N]
// mode 1: C remapped to per-head layout [bh, t, d]
// ---------------------------------------------------------------------------
__global__ __launch_bounds__(256)
void sgemm_k(const float* __restrict__ A, const float* __restrict__ B,
             float* __restrict__ C, int M, int N, int K, int mode)
{
    __shared__ __align__(16) float As[8][128];
    __shared__ __align__(16) float Bs[8][128];

    const int tid  = threadIdx.x;
    const int brow = blockIdx.y * 128;
    const int bcol = blockIdx.x * 128;
    const int tr   = (tid >> 4) * 8;
    const int tc   = (tid & 15) * 8;

    const int a_row = tid >> 1;
    const int a_col = (tid & 1) * 4;
    const int b_row = tid >> 5;
    const int b_col = (tid & 31) * 4;

    const float* Ap = A + (size_t)(brow + a_row) * K + a_col;
    const float* Bp = B + (size_t)b_row * N + bcol + b_col;

    u64 acc2[4][8];
#pragma unroll
    for (int y = 0; y < 4; y++)
#pragma unroll
        for (int x = 0; x < 8; x++) acc2[y][x] = 0ull;

    // prologue: first tile's loads
    float4 av = *(const float4*)Ap;  Ap += 8;
    float4 bv = *(const float4*)Bp;  Bp += (size_t)8 * N;

    for (int k0 = 0; k0 < K; k0 += 8) {
        As[a_col + 0][a_row] = av.x;
        As[a_col + 1][a_row] = av.y;
        As[a_col + 2][a_row] = av.z;
        As[a_col + 3][a_row] = av.w;
        *(float4*)&Bs[b_row][b_col] = bv;
        __syncthreads();

        // prefetch next K-tile while computing this one
        if (k0 + 8 < K) {
            av = *(const float4*)Ap;  Ap += 8;
            bv = *(const float4*)Bp;  Bp += (size_t)8 * N;
        }

#pragma unroll
        for (int kk = 0; kk < 8; kk++) {
            const u64* a64 = (const u64*)&As[kk][tr];   // 32B-aligned (tr % 8 == 0)
            u64 ap[4];
#pragma unroll
            for (int y = 0; y < 4; y++) ap[y] = a64[y];

            float4 b0 = *(const float4*)&Bs[kk][tc];
            float4 b1 = *(const float4*)&Bs[kk][tc + 4];
            float br[8] = {b0.x, b0.y, b0.z, b0.w, b1.x, b1.y, b1.z, b1.w};
#pragma unroll
            for (int x = 0; x < 8; x++) {
                u64 bb = bcast2(br[x]);
#pragma unroll
                for (int y = 0; y < 4; y++) fma2(acc2[y][x], ap[y], bb);
            }
        }
        __syncthreads();
    }

    // unpack pairs -> per-row values
    float val[8][8];
#pragma unroll
    for (int y2 = 0; y2 < 4; y2++)
#pragma unroll
        for (int x = 0; x < 8; x++) {
            float2 f = unpack2(acc2[y2][x]);
            val[2 * y2 + 0][x] = f.x;
            val[2 * y2 + 1][x] = f.y;
        }

    if (mode == 0) {
#pragma unroll
        for (int y = 0; y < 8; y++) {
            float* cp = C + (size_t)(brow + tr + y) * N + bcol + tc;
            *(float4*)(cp)     = make_float4(val[y][0], val[y][1], val[y][2], val[y][3]);
            *(float4*)(cp + 4) = make_float4(val[y][4], val[y][5], val[y][6], val[y][7]);
        }
    } else {
#pragma unroll
        for (int y = 0; y < 8; y++) {
            int m = brow + tr + y;
            int b = m >> 12;           // / T
            int t = m & (TT - 1);
            int col0 = bcol + tc;
            int n = col0 >> 6;
            int d = col0 & 63;
            float* cp = C + (((size_t)(b * NHEADS + n) * TT + t) * DPH + d);
            *(float4*)(cp)     = make_float4(val[y][0], val[y][1], val[y][2], val[y][3]);
            *(float4*)(cp + 4) = make_float4(val[y][4], val[y][5], val[y][6], val[y][7]);
        }
    }
}

// ---------------------------------------------------------------------------
// LSH bucketize: per token compute 64 rotations, argmax over [r, -r] per hash.
// ---------------------------------------------------------------------------
__global__ __launch_bounds__(128)
void bucketize_k(const float* __restrict__ rot)
{
    __shared__ __align__(16) float rs[DPH * 64];   // rot[d][h*32+r], 16 KB
    const int tid = threadIdx.x;
    for (int x = tid; x < DPH * 64; x += 128) rs[x] = rot[x];
    __syncthreads();

    const int gid = blockIdx.x * 128 + tid;     // 0 .. BH*T-1
    const int bh  = gid >> 12;
    const int t   = gid & (TT - 1);

    const float* qrow = g_qk + ((size_t)bh * TT + t) * DPH;

    u64 vals2[32];
#pragma unroll
    for (int x = 0; x < 32; x++) vals2[x] = 0ull;

    for (int d = 0; d < DPH; d++) {
        u64 qb = bcast2(qrow[d]);
        const u64* rr = (const u64*)(rs + d * 64);   // 256B-aligned rows
#pragma unroll
        for (int x = 0; x < 32; x++) fma2(vals2[x], qb, rr[x]);
    }

    float vals[64];
#pragma unroll
    for (int x = 0; x < 32; x++) {
        float2 f = unpack2(vals2[x]);
        vals[2 * x] = f.x; vals[2 * x + 1] = f.y;
    }

#pragma unroll
    for (int h = 0; h < NHASH; h++) {
        float best = -INFINITY;
        int   bi   = 0;
#pragma unroll
        for (int idx = 0; idx < 64; idx++) {
            float vv = (idx < 32) ? vals[h * 32 + idx] : -vals[h * 32 + idx - 32];
            if (vv > best) { best = vv; bi = idx; }   // first max wins (jnp.argmax)
        }
        g_bkt[((size_t)(bh * NHASH + h)) * TT + t] = (unsigned char)bi;
    }
}

// ---------------------------------------------------------------------------
// Stable counting sort of 4096 tokens by bucket (64 bins), per (bh, hash).
// ---------------------------------------------------------------------------
__global__ __launch_bounds__(128)
void sort_k()
{
    const int seg = blockIdx.x;        // bh*2 + h
    const int tid = threadIdx.x;
    __shared__ int hist[NBUCK * 128];  // [bucket][thread]
    __shared__ int btot[NBUCK];

    const unsigned char* bk = g_bkt + (size_t)seg * TT;

    for (int x = tid; x < NBUCK * 128; x += 128) hist[x] = 0;
    __syncthreads();

    const int t0 = tid * 32;
    for (int j = 0; j < 32; j++) {
        int b = bk[t0 + j];
        hist[b * 128 + tid]++;
    }
    __syncthreads();

    if (tid < NBUCK) {
        int s = 0;
        for (int j = 0; j < 128; j++) s += hist[tid * 128 + j];
        btot[tid] = s;
    }
    __syncthreads();

    if (tid == 0) {
        int run = 0;
        for (int b = 0; b < NBUCK; b++) { int c = btot[b]; btot[b] = run; run += c; }
    }
    __syncthreads();

    if (tid < NBUCK) {
        int run = btot[tid];
        for (int j = 0; j < 128; j++) {
            int c = hist[tid * 128 + j];
            hist[tid * 128 + j] = run;
            run += c;
        }
    }
    __syncthreads();

    int* dst = g_st + (size_t)(seg >> 1) * (NHASH * TT) + (size_t)(seg & 1) * TT;
    for (int j = 0; j < 32; j++) {
        int t = t0 + j;
        int b = bk[t];
        int pos = hist[b * 128 + tid]++;
        dst[pos] = t;
    }
}

// ---------------------------------------------------------------------------
// Chunked LSH attention with one-chunk look-back (FFMA2 inner loops).
// grid = (128 chunks, 64 bh), block = 64 threads (one per query row).
// ---------------------------------------------------------------------------
__global__ __launch_bounds__(64)
void attn_k(const unsigned char* __restrict__ pad)
{
    const int c  = blockIdx.x;
    const int bh = blockIdx.y;
    const int i  = threadIdx.x;
    const int b  = bh >> 4;

    __shared__ __align__(16) float ks[WW][68];  // 272B row stride (16B aligned)
    __shared__ __align__(16) float vs[WW][68];
    __shared__ int   tks[WW];
    __shared__ float pen[WW];

    const int* stb = g_st + (size_t)bh * (NHASH * TT);

    const int sq = c * WW + i;
    const int tq = stb[sq];

    u64 qp[32];
    {
        const u64* qrow = (const u64*)(g_qk + ((size_t)bh * TT + tq) * DPH);
#pragma unroll
        for (int x = 0; x < 32; x++) qp[x] = qrow[x];
    }

    float m = -INFINITY, l = 0.f;
    u64 accp[32];
#pragma unroll
    for (int d = 0; d < 32; d++) accp[d] = 0ull;

    for (int stg = 0; stg < 2; stg++) {
        const int kc = (stg == 0) ? c : ((c + CCHUNK - 1) & (CCHUNK - 1));
        const int sk = kc * WW + i;
        const int tk = stb[sk];

        {
            const float4* krow = (const float4*)(g_qk + ((size_t)bh * TT + tk) * DPH);
            const float4* vrow = (const float4*)(g_v  + ((size_t)bh * TT + tk) * DPH);
            float4 kr[16];
            float ss = 0.f;
#pragma unroll
            for (int x = 0; x < 16; x++) {
                kr[x] = krow[x];
                ss += kr[x].x * kr[x].x + kr[x].y * kr[x].y
                    + kr[x].z * kr[x].z + kr[x].w * kr[x].w;
            }
            float inv = 1.f / fmaxf(sqrtf(ss), 1e-6f);
#pragma unroll
            for (int x = 0; x < 16; x++) {
                *(float4*)&ks[i][4 * x] = make_float4(kr[x].x * inv, kr[x].y * inv,
                                                      kr[x].z * inv, kr[x].w * inv);
                *(float4*)&vs[i][4 * x] = vrow[x];
            }
            tks[i] = tk;
            pen[i] = pad[(size_t)b * TT + tk] ? -1e9f : 0.f;
        }
        __syncthreads();

        for (int j = 0; j < WW; j++) {
            const u64* kj = (const u64*)&ks[j][0];
            u64 s2 = 0ull;
#pragma unroll
            for (int x = 0; x < 32; x++) fma2(s2, qp[x], kj[x]);
            float2 sp = unpack2(s2);
            float s = (sp.x + sp.y) * 0.125f + pen[j];
            if (tq == tks[j]) s -= 1e5f;

            const u64* vj = (const u64*)&vs[j][0];
            if (s <= m) {
                float p = __expf(s - m);
                l += p;
                u64 pb = bcast2(p);
#pragma unroll
                for (int d = 0; d < 32; d++) fma2(accp[d], pb, vj[d]);
            } else {
                float sc = __expf(m - s);   // exp(-inf)=0 handles first iter
                l = l * sc + 1.f;
                u64 scb = bcast2(sc);
#pragma unroll
                for (int d = 0; d < 32; d++) accp[d] = fma2o(accp[d], scb, vj[d]);
                m = s;
            }
        }
        __syncthreads();
    }

    const float lse  = m + __logf(l);
    const float invl = 1.f / l;
    const int   h    = sq >> 12;     // sorted index / T

    float* orow = g_o + (((size_t)(bh * NHASH + h)) * TT + tq) * DPH;
#pragma unroll
    for (int d = 0; d < 32; d++) {
        float2 f = unpack2(accp[d]);
        orow[2 * d]     = f.x * invl;
        orow[2 * d + 1] = f.y * invl;
    }
    g_lse[((size_t)(bh * NHASH + h)) * TT + tq] = lse;
}

// ---------------------------------------------------------------------------
// Combine the NHASH=2 rounds with softmax(lse) weights; write [b,t,n,d]
// into g_qk (reused -- qk data is dead after attn_k).
// ---------------------------------------------------------------------------
__global__ __launch_bounds__(256)
void combine_k()
{
    const size_t idx = (size_t)blockIdx.x * 256 + threadIdx.x; // BH*T*DPH
    const int d   = (int)(idx & 63);
    const size_t row = idx >> 6;           // bh*T + t
    const int bh  = (int)(row >> 12);
    const int t   = (int)(row & (TT - 1));

    const float l0 = g_lse[((size_t)(bh * 2 + 0)) * TT + t];
    const float l1 = g_lse[((size_t)(bh * 2 + 1)) * TT + t];
    const float mm = fmaxf(l0, l1);
    const float e0 = __expf(l0 - mm), e1 = __expf(l1 - mm);
    const float inv = 1.f / (e0 + e1);

    const float v0 = g_o[(((size_t)(bh * 2 + 0)) * TT + t) * DPH + d];
    const float v1 = g_o[(((size_t)(bh * 2 + 1)) * TT + t) * DPH + d];

    const int b = bh >> 4, n = bh & 15;
    g_qk[(((size_t)(b * TT + t)) * NHEADS + n) * DPH + d] = (e0 * v0 + e1 * v1) * inv;
}

// ---------------------------------------------------------------------------
// Host entry
// ---------------------------------------------------------------------------
extern "C" void kernel_launch(void* const* d_in, const int* in_sizes, int n_in,
                              void* d_out, int out_size)
{
    const float*         x    = (const float*)d_in[0];         // [B,T,H]
    const unsigned char* pad  = (const unsigned char*)d_in[1]; // [B,T] bool
    const float*         wqk  = (const float*)d_in[2];         // [H,NH,DPH] -> [1024,1024]
    const float*         wv   = (const float*)d_in[3];
    const float*         wo   = (const float*)d_in[4];         // [NH,DPH,H] -> [1024,1024]
    const float*         rot  = (const float*)d_in[5];         // [DPH,2,32]
    float*               out  = (float*)d_out;                 // [B,T,H]

    void *p_qk, *p_v;
    cudaGetSymbolAddress(&p_qk, g_qk);
    cudaGetSymbolAddress(&p_v,  g_v);

    // 1) qk / v projections: [16384,1024] x [1024,1024], remapped epilogue
    dim3 gg(HID / 128, MTOT / 128);
    sgemm_k<<<gg, 256>>>(x, wqk, (float*)p_qk, MTOT, HID, HID, 1);
    sgemm_k<<<gg, 256>>>(x, wv,  (float*)p_v,  MTOT, HID, HID, 1);

    // 2) LSH bucketing
    bucketize_k<<<(BH * TT) / 128, 128>>>(rot);

    // 3) stable counting sort per (bh, hash)
    sort_k<<<BH * NHASH, 128>>>();

    // 4) chunked attention with look-back
    dim3 ga(CCHUNK, BH);
    attn_k<<<ga, 64>>>(pad);

    // 5) combine hash rounds -> [b,t,n,d] into g_qk (reuse)
    combine_k<<<((size_t)BH * TT * DPH) / 256, 256>>>();

    // 6) output projection
    sgemm_k<<<gg, 256>>>((const float*)p_qk, wo, out, MTOT, HID, HID, 0);
}

// round 10
// speedup vs baseline: 1.2813x; 1.2659x over previous
#include <cuda_runtime.h>
#include <cuda_bf16.h>
#include <mma.h>
#include <math.h>

using namespace nvcuda;

// ---------------------------------------------------------------------------
// Problem constants (fixed shapes from setup_inputs)
// ---------------------------------------------------------------------------
#define TT      4096   // sequence length T
#define NHEADS  16
#define BB      4      // batch
#define BH      64     // B * NHEADS
#define DPH     64     // head dim
#define HID     1024   // hidden H
#define NHASH   2
#define NBUCK   64     // n_buckets
#define WW      64     // bucket_size W
#define CCHUNK  128    // NHASH * NBUCK chunks per bh
#define MTOT    16384  // B * T rows of the big GEMMs

typedef unsigned long long u64;

// ---- packed fp32x2 helpers ------------------------------------------------
__device__ __forceinline__ void fma2(u64& d, u64 a, u64 b) {
    asm("fma.rn.f32x2 %0, %1, %2, %0;" : "+l"(d) : "l"(a), "l"(b));
}
__device__ __forceinline__ u64 fma2o(u64 a, u64 b, u64 c) {
    u64 d; asm("fma.rn.f32x2 %0, %1, %2, %3;" : "=l"(d) : "l"(a), "l"(b), "l"(c));
    return d;
}
__device__ __forceinline__ u64 bcast2(float f) {
    u64 r; unsigned int u = __float_as_uint(f);
    asm("mov.b64 %0, {%1, %1};" : "=l"(r) : "r"(u));
    return r;
}
__device__ __forceinline__ float2 unpack2(u64 v) {
    unsigned int lo, hi;
    asm("mov.b64 {%0, %1}, %2;" : "=r"(lo), "=r"(hi) : "l"(v));
    return make_float2(__uint_as_float(lo), __uint_as_float(hi));
}

// ---------------------------------------------------------------------------
// Device scratch (static; no cudaMalloc allowed).
// g_qk is reused as the combine output buffer [b,t,n,d] after attention.
// ---------------------------------------------------------------------------
__device__ float          g_qk  [(size_t)BH * TT * DPH];          //  67 MB (later: comb)
__device__ float          g_v   [(size_t)BH * TT * DPH];          //  67 MB
__device__ float          g_o   [(size_t)BH * NHASH * TT * DPH];  // 134 MB
__device__ float          g_lse [(size_t)BH * NHASH * TT];        //   2 MB
__device__ int            g_st  [(size_t)BH * NHASH * TT];        //   2 MB
__device__ unsigned char  g_bkt [(size_t)BH * NHASH * TT];        // 512 KB

// ===========================================================================
// SCALAR fp32 SGEMM (known-good from R4/R5) -- used ONLY for qk (the LSH-
// decision-critical path needs exact fp32; tensor-core accumulation loses
// correction terms).  128x128x8 tile, 256 threads, 8x8/thread, reg-prefetch.
// Writes C remapped per-head: m=b*T+t, col=n*64+d -> C[((b*16+n)*T+t)*64+d].
// ===========================================================================
__global__ __launch_bounds__(256)
void sgemm_qk_k(const float* __restrict__ A, const float* __restrict__ B,
                float* __restrict__ C, int M, int N, int K)
{
    __shared__ __align__(16) float As[8][128];
    __shared__ __align__(16) float Bs[8][128];

    const int tid  = threadIdx.x;
    const int brow = blockIdx.y * 128;
    const int bcol = blockIdx.x * 128;
    const int tr   = (tid >> 4) * 8;
    const int tc   = (tid & 15) * 8;

    const int a_row = tid >> 1;
    const int a_col = (tid & 1) * 4;
    const int b_row = tid >> 5;
    const int b_col = (tid & 31) * 4;

    const float* Ap = A + (size_t)(brow + a_row) * K + a_col;
    const float* Bp = B + (size_t)b_row * N + bcol + b_col;

    float acc[8][8];
#pragma unroll
    for (int y = 0; y < 8; y++)
#pragma unroll
        for (int x = 0; x < 8; x++) acc[y][x] = 0.f;

    float4 av = *(const float4*)Ap;  Ap += 8;
    float4 bv = *(const float4*)Bp;  Bp += (size_t)8 * N;

    for (int k0 = 0; k0 < K; k0 += 8) {
        As[a_col + 0][a_row] = av.x;
        As[a_col + 1][a_row] = av.y;
        As[a_col + 2][a_row] = av.z;
        As[a_col + 3][a_row] = av.w;
        *(float4*)&Bs[b_row][b_col] = bv;
        __syncthreads();

        if (k0 + 8 < K) {
            av = *(const float4*)Ap;  Ap += 8;
            bv = *(const float4*)Bp;  Bp += (size_t)8 * N;
        }

#pragma unroll
        for (int kk = 0; kk < 8; kk++) {
            float4 a0 = *(const float4*)&As[kk][tr];
            float4 a1 = *(const float4*)&As[kk][tr + 4];
            float4 b0 = *(const float4*)&Bs[kk][tc];
            float4 b1 = *(const float4*)&Bs[kk][tc + 4];
            float ar[8] = {a0.x, a0.y, a0.z, a0.w, a1.x, a1.y, a1.z, a1.w};
            float br[8] = {b0.x, b0.y, b0.z, b0.w, b1.x, b1.y, b1.z, b1.w};
#pragma unroll
            for (int y = 0; y < 8; y++)
#pragma unroll
                for (int x = 0; x < 8; x++) acc[y][x] += ar[y] * br[x];
        }
        __syncthreads();
    }

#pragma unroll
    for (int y = 0; y < 8; y++) {
        int m = brow + tr + y;
        int b = m >> 12;           // / T
        int t = m & (TT - 1);
        int col0 = bcol + tc;
        int n = col0 >> 6;
        int d = col0 & 63;
        float* cp = C + (((size_t)(b * NHEADS + n) * TT + t) * DPH + d);
        *(float4*)(cp)     = make_float4(acc[y][0], acc[y][1], acc[y][2], acc[y][3]);
        *(float4*)(cp + 4) = make_float4(acc[y][4], acc[y][5], acc[y][6], acc[y][7]);
    }
}

// ===========================================================================
// bf16 tensor-core GEMM, 3-term split: D = A0B0 + A0B1 + A1B0  (~1e-5..1e-4)
// Used ONLY for the linear paths (v projection, output projection) where the
// error flows additively into the output (no discrete decisions).
// 128x128 block tile, 8 warps (64x32 warp tiles), wmma m16n16k16, KSTEP=16.
// mode 0: C row-major [M,N];  mode 1: per-head remap (ld=64 in-tile).
// ===========================================================================
#define KSTEP 16
#define LDA   24    // 16 + 8 pad (48B rows; 16B multiple)
#define LDB   136   // 128 + 8 pad (272B rows; 16B multiple)

static_assert((2 * 128 * LDA + 2 * KSTEP * LDB) * 2 <= 48 * 1024, "smem");

__device__ __forceinline__ void split2(float a, __nv_bfloat16& c0, __nv_bfloat16& c1)
{
    c0 = __float2bfloat16_rn(a);
    c1 = __float2bfloat16_rn(a - __bfloat162float(c0));
}

__global__ __launch_bounds__(256)
void tgemm_k(const float* __restrict__ A, const float* __restrict__ B,
             float* __restrict__ C, int M, int N, int K, int mode)
{
    __shared__ __align__(32) __nv_bfloat16 As[2][128][LDA];
    __shared__ __align__(32) __nv_bfloat16 Bs[2][KSTEP][LDB];

    const int tid  = threadIdx.x;
    const int wid  = tid >> 5;
    const int brow = blockIdx.y * 128;
    const int bcol = blockIdx.x * 128;
    const int wm   = (wid >> 2) * 64;   // warp tile row offset (0 or 64)
    const int wn   = (wid & 3) * 32;    // warp tile col offset (0/32/64/96)

    const int a_row  = tid >> 1;              // 0..127
    const int a_col  = (tid & 1) * 8;         // 0 or 8
    const int b_row  = tid >> 4;              // 0..15
    const int b_col  = (tid & 15) * 8;        // 0..120

    const float* Ap = A + (size_t)(brow + a_row) * K + a_col;
    const float* Bp = B + (size_t)b_row * N + bcol + b_col;

    wmma::fragment<wmma::accumulator, 16, 16, 16, float> acc[4][2];
#pragma unroll
    for (int mi = 0; mi < 4; mi++)
#pragma unroll
        for (int ni = 0; ni < 2; ni++) wmma::fill_fragment(acc[mi][ni], 0.f);

    float4 av0 = *(const float4*)(Ap);
    float4 av1 = *(const float4*)(Ap + 4);
    float4 bv0 = *(const float4*)(Bp);
    float4 bv1 = *(const float4*)(Bp + 4);
    Ap += KSTEP;
    Bp += (size_t)KSTEP * N;

    for (int k0 = 0; k0 < K; k0 += KSTEP) {
        {
            float va[8] = {av0.x, av0.y, av0.z, av0.w, av1.x, av1.y, av1.z, av1.w};
#pragma unroll
            for (int j = 0; j < 8; j++) {
                __nv_bfloat16 c0, c1;
                split2(va[j], c0, c1);
                As[0][a_row][a_col + j] = c0;
                As[1][a_row][a_col + j] = c1;
            }
            float vb[8] = {bv0.x, bv0.y, bv0.z, bv0.w, bv1.x, bv1.y, bv1.z, bv1.w};
#pragma unroll
            for (int j = 0; j < 8; j++) {
                __nv_bfloat16 c0, c1;
                split2(vb[j], c0, c1);
                Bs[0][b_row][b_col + j] = c0;
                Bs[1][b_row][b_col + j] = c1;
            }
        }
        __syncthreads();

        if (k0 + KSTEP < K) {
            av0 = *(const float4*)(Ap);
            av1 = *(const float4*)(Ap + 4);
            bv0 = *(const float4*)(Bp);
            bv1 = *(const float4*)(Bp + 4);
            Ap += KSTEP;
            Bp += (size_t)KSTEP * N;
        }

        wmma::fragment<wmma::matrix_b, 16, 16, 16, __nv_bfloat16, wmma::row_major> bf[2][2];
#pragma unroll
        for (int ni = 0; ni < 2; ni++) {
            wmma::load_matrix_sync(bf[ni][0], &Bs[0][0][wn + ni * 16], LDB);
            wmma::load_matrix_sync(bf[ni][1], &Bs[1][0][wn + ni * 16], LDB);
        }

#pragma unroll
        for (int mi = 0; mi < 4; mi++) {
            wmma::fragment<wmma::matrix_a, 16, 16, 16, __nv_bfloat16, wmma::row_major> af0, af1;
            wmma::load_matrix_sync(af0, &As[0][wm + mi * 16][0], LDA);
            wmma::load_matrix_sync(af1, &As[1][wm + mi * 16][0], LDA);
#pragma unroll
            for (int ni = 0; ni < 2; ni++) {
                wmma::mma_sync(acc[mi][ni], af0, bf[ni][0], acc[mi][ni]);
                wmma::mma_sync(acc[mi][ni], af0, bf[ni][1], acc[mi][ni]);
                wmma::mma_sync(acc[mi][ni], af1, bf[ni][0], acc[mi][ni]);
            }
        }
        __syncthreads();
    }

#pragma unroll
    for (int mi = 0; mi < 4; mi++) {
#pragma unroll
        for (int ni = 0; ni < 2; ni++) {
            int m0 = brow + wm + mi * 16;
            int c0 = bcol + wn + ni * 16;
            if (mode == 0) {
                wmma::store_matrix_sync(C + (size_t)m0 * N + c0, acc[mi][ni], N,
                                        wmma::mem_row_major);
            } else {
                int b = m0 >> 12;
                int t = m0 & (TT - 1);
                int n = c0 >> 6;
                int d = c0 & 63;
                float* cp = C + (((size_t)(b * NHEADS + n) * TT + t) * DPH + d);
                wmma::store_matrix_sync(cp, acc[mi][ni], DPH, wmma::mem_row_major);
            }
        }
    }
}

// ---------------------------------------------------------------------------
// LSH bucketize: per token compute 64 rotations, argmax over [r, -r] per hash.
// ---------------------------------------------------------------------------
__global__ __launch_bounds__(128)
void bucketize_k(const float* __restrict__ rot)
{
    __shared__ __align__(16) float rs[DPH * 64];   // rot[d][h*32+r], 16 KB
    const int tid = threadIdx.x;
    for (int x = tid; x < DPH * 64; x += 128) rs[x] = rot[x];
    __syncthreads();

    const int gid = blockIdx.x * 128 + tid;     // 0 .. BH*T-1
    const int bh  = gid >> 12;
    const int t   = gid & (TT - 1);

    const float* qrow = g_qk + ((size_t)bh * TT + t) * DPH;

    u64 vals2[32];
#pragma unroll
    for (int x = 0; x < 32; x++) vals2[x] = 0ull;

    for (int d = 0; d < DPH; d++) {
        u64 qb = bcast2(qrow[d]);
        const u64* rr = (const u64*)(rs + d * 64);
#pragma unroll
        for (int x = 0; x < 32; x++) fma2(vals2[x], qb, rr[x]);
    }

    float vals[64];
#pragma unroll
    for (int x = 0; x < 32; x++) {
        float2 f = unpack2(vals2[x]);
        vals[2 * x] = f.x; vals[2 * x + 1] = f.y;
    }

#pragma unroll
    for (int h = 0; h < NHASH; h++) {
        float best = -INFINITY;
        int   bi   = 0;
#pragma unroll
        for (int idx = 0; idx < 64; idx++) {
            float vv = (idx < 32) ? vals[h * 32 + idx] : -vals[h * 32 + idx - 32];
            if (vv > best) { best = vv; bi = idx; }   // first max wins (jnp.argmax)
        }
        g_bkt[((size_t)(bh * NHASH + h)) * TT + t] = (unsigned char)bi;
    }
}

// ---------------------------------------------------------------------------
// Stable counting sort of 4096 tokens by bucket (64 bins), per (bh, hash).
// ---------------------------------------------------------------------------
__global__ __launch_bounds__(128)
void sort_k()
{
    const int seg = blockIdx.x;        // bh*2 + h
    const int tid = threadIdx.x;
    __shared__ int hist[NBUCK * 128];  // [bucket][thread]
    __shared__ int btot[NBUCK];

    const unsigned char* bk = g_bkt + (size_t)seg * TT;

    for (int x = tid; x < NBUCK * 128; x += 128) hist[x] = 0;
    __syncthreads();

    const int t0 = tid * 32;
    for (int j = 0; j < 32; j++) {
        int b = bk[t0 + j];
        hist[b * 128 + tid]++;
    }
    __syncthreads();

    if (tid < NBUCK) {
        int s = 0;
        for (int j = 0; j < 128; j++) s += hist[tid * 128 + j];
        btot[tid] = s;
    }
    __syncthreads();

    if (tid == 0) {
        int run = 0;
        for (int b = 0; b < NBUCK; b++) { int c = btot[b]; btot[b] = run; run += c; }
    }
    __syncthreads();

    if (tid < NBUCK) {
        int run = btot[tid];
        for (int j = 0; j < 128; j++) {
            int c = hist[tid * 128 + j];
            hist[tid * 128 + j] = run;
            run += c;
        }
    }
    __syncthreads();

    int* dst = g_st + (size_t)(seg >> 1) * (NHASH * TT) + (size_t)(seg & 1) * TT;
    for (int j = 0; j < 32; j++) {
        int t = t0 + j;
        int b = bk[t];
        int pos = hist[b * 128 + tid]++;
        dst[pos] = t;
    }
}

// ---------------------------------------------------------------------------
// Chunked LSH attention with one-chunk look-back.
// grid = (128 chunks, 64 bh), block = 64 threads (one per query row).
// ---------------------------------------------------------------------------
__global__ __launch_bounds__(64)
void attn_k(const unsigned char* __restrict__ pad)
{
    const int c  = blockIdx.x;
    const int bh = blockIdx.y;
    const int i  = threadIdx.x;
    const int b  = bh >> 4;

    __shared__ __align__(16) float ks[WW][68];
    __shared__ __align__(16) float vs[WW][68];
    __shared__ int   tks[WW];
    __shared__ float pen[WW];

    const int* stb = g_st + (size_t)bh * (NHASH * TT);

    const int sq = c * WW + i;
    const int tq = stb[sq];

    u64 qp[32];
    {
        const u64* qrow = (const u64*)(g_qk + ((size_t)bh * TT + tq) * DPH);
#pragma unroll
        for (int x = 0; x < 32; x++) qp[x] = qrow[x];
    }

    float m = -INFINITY, l = 0.f;
    u64 accp[32];
#pragma unroll
    for (int d = 0; d < 32; d++) accp[d] = 0ull;

    for (int stg = 0; stg < 2; stg++) {
        const int kc = (stg == 0) ? c : ((c + CCHUNK - 1) & (CCHUNK - 1));
        const int sk = kc * WW + i;
        const int tk = stb[sk];

        {
            const float4* krow = (const float4*)(g_qk + ((size_t)bh * TT + tk) * DPH);
            const float4* vrow = (const float4*)(g_v  + ((size_t)bh * TT + tk) * DPH);
            float4 kr[16];
            float ss = 0.f;
#pragma unroll
            for (int x = 0; x < 16; x++) {
                kr[x] = krow[x];
                ss += kr[x].x * kr[x].x + kr[x].y * kr[x].y
                    + kr[x].z * kr[x].z + kr[x].w * kr[x].w;
            }
            float inv = 1.f / fmaxf(sqrtf(ss), 1e-6f);
#pragma unroll
            for (int x = 0; x < 16; x++) {
                *(float4*)&ks[i][4 * x] = make_float4(kr[x].x * inv, kr[x].y * inv,
                                                      kr[x].z * inv, kr[x].w * inv);
                *(float4*)&vs[i][4 * x] = vrow[x];
            }
            tks[i] = tk;
            pen[i] = pad[(size_t)b * TT + tk] ? -1e9f : 0.f;
        }
        __syncthreads();

        for (int j = 0; j < WW; j++) {
            const u64* kj = (const u64*)&ks[j][0];
            u64 s2 = 0ull;
#pragma unroll
            for (int x = 0; x < 32; x++) fma2(s2, qp[x], kj[x]);
            float2 sp = unpack2(s2);
            float s = (sp.x + sp.y) * 0.125f + pen[j];
            if (tq == tks[j]) s -= 1e5f;

            const u64* vj = (const u64*)&vs[j][0];
            if (s <= m) {
                float p = __expf(s - m);
                l += p;
                u64 pb = bcast2(p);
#pragma unroll
                for (int d = 0; d < 32; d++) fma2(accp[d], pb, vj[d]);
            } else {
                float sc = __expf(m - s);   // exp(-inf)=0 handles first iter
                l = l * sc + 1.f;
                u64 scb = bcast2(sc);
#pragma unroll
                for (int d = 0; d < 32; d++) accp[d] = fma2o(accp[d], scb, vj[d]);
                m = s;
            }
        }
        __syncthreads();
    }

    const float lse  = m + __logf(l);
    const float invl = 1.f / l;
    const int   h    = sq >> 12;     // sorted index / T

    float* orow = g_o + (((size_t)(bh * NHASH + h)) * TT + tq) * DPH;
#pragma unroll
    for (int d = 0; d < 32; d++) {
        float2 f = unpack2(accp[d]);
        orow[2 * d]     = f.x * invl;
        orow[2 * d + 1] = f.y * invl;
    }
    g_lse[((size_t)(bh * NHASH + h)) * TT + tq] = lse;
}

// ---------------------------------------------------------------------------
// Combine the NHASH=2 rounds with softmax(lse) weights; write [b,t,n,d]
// into g_qk (reused -- qk data is dead after attn_k).
// ---------------------------------------------------------------------------
__global__ __launch_bounds__(256)
void combine_k()
{
    const size_t idx = (size_t)blockIdx.x * 256 + threadIdx.x; // BH*T*DPH
    const int d   = (int)(idx & 63);
    const size_t row = idx >> 6;           // bh*T + t
    const int bh  = (int)(row >> 12);
    const int t   = (int)(row & (TT - 1));

    const float l0 = g_lse[((size_t)(bh * 2 + 0)) * TT + t];
    const float l1 = g_lse[((size_t)(bh * 2 + 1)) * TT + t];
    const float mm = fmaxf(l0, l1);
    const float e0 = __expf(l0 - mm), e1 = __expf(l1 - mm);
    const float inv = 1.f / (e0 + e1);

    const float v0 = g_o[(((size_t)(bh * 2 + 0)) * TT + t) * DPH + d];
    const float v1 = g_o[(((size_t)(bh * 2 + 1)) * TT + t) * DPH + d];

    const int b = bh >> 4, n = bh & 15;
    g_qk[(((size_t)(b * TT + t)) * NHEADS + n) * DPH + d] = (e0 * v0 + e1 * v1) * inv;
}

// ---------------------------------------------------------------------------
// Host entry
// ---------------------------------------------------------------------------
extern "C" void kernel_launch(void* const* d_in, const int* in_sizes, int n_in,
                              void* d_out, int out_size)
{
    const float*         x    = (const float*)d_in[0];         // [B,T,H]
    const unsigned char* pad  = (const unsigned char*)d_in[1]; // [B,T] bool
    const float*         wqk  = (const float*)d_in[2];         // [H,NH,DPH] -> [1024,1024]
    const float*         wv   = (const float*)d_in[3];
    const float*         wo   = (const float*)d_in[4];         // [NH,DPH,H] -> [1024,1024]
    const float*         rot  = (const float*)d_in[5];         // [DPH,2,32]
    float*               out  = (float*)d_out;                 // [B,T,H]

    void *p_qk, *p_v;
    cudaGetSymbolAddress(&p_qk, g_qk);
    cudaGetSymbolAddress(&p_v,  g_v);

    dim3 gg(HID / 128, MTOT / 128);
    // 1) qk projection: EXACT fp32 scalar path (feeds LSH argmax decisions)
    sgemm_qk_k<<<gg, 256>>>(x, wqk, (float*)p_qk, MTOT, HID, HID);
    // v projection: bf16 3-term tensor path (linear, error-tolerant)
    tgemm_k<<<gg, 256>>>(x, wv, (float*)p_v, MTOT, HID, HID, 1);

    // 2) LSH bucketing
    bucketize_k<<<(BH * TT) / 128, 128>>>(rot);

    // 3) stable counting sort per (bh, hash)
    sort_k<<<BH * NHASH, 128>>>();

    // 4) chunked attention with look-back
    dim3 ga(CCHUNK, BH);
    attn_k<<<ga, 64>>>(pad);

    // 5) combine hash rounds -> [b,t,n,d] into g_qk (reuse)
    combine_k<<<((size_t)BH * TT * DPH) / 256, 256>>>();

    // 6) output projection: bf16 3-term tensor path
    tgemm_k<<<gg, 256>>>((const float*)p_qk, wo, out, MTOT, HID, HID, 0);
}